// round 1
// baseline (speedup 1.0000x reference)
#include <cuda_runtime.h>
#include <cuda_bf16.h>

// ---------------------------------------------------------------------------
// TensorizedEmbedding: out[b] = core0[d0] x core1[d1] x core2[d2] x core3[d3]
// ROW_DIMS=(8,10,20,20), COL_DIMS=(4,4,6,8), RANKS=(1,16,16,16,1)
// Strategy: pre-contract into T01[80][16r][16a] and T23[400][16r][48c],
// then per token a 16x48x16 GEMM from shared memory.
// ---------------------------------------------------------------------------

static __device__ float g_T01[80 * 256];    // [(d0*10+d1)][r2][a]  (a = m0*4+m1)
static __device__ float g_T23[400 * 768];   // [(d2*20+d3)][r2][c]  (c = m2*8+m3)

// T01[comb][r2][a] = sum_{r1} core0[0,d0,m0,r1] * core1[r1,d1,m1,r2]
__global__ void precompute_T01(const float* __restrict__ core0,
                               const float* __restrict__ core1) {
    int comb = blockIdx.x;            // 0..79
    int d0 = comb / 10, d1 = comb % 10;
    int e  = threadIdx.x;             // 0..255
    int r2 = e >> 4;                  // 0..15
    int a  = e & 15;                  // m0*4 + m1
    int m0 = a >> 2, m1 = a & 3;
    float s = 0.f;
#pragma unroll
    for (int r1 = 0; r1 < 16; ++r1) {
        float v0 = core0[(d0 * 4 + m0) * 16 + r1];             // [1,8,4,16]
        float v1 = core1[((r1 * 10 + d1) * 4 + m1) * 16 + r2]; // [16,10,4,16]
        s += v0 * v1;
    }
    g_T01[comb * 256 + r2 * 16 + a] = s;
}

// T23[comb][r2][c] = sum_{r3} core2[r2,d2,m2,r3] * core3[r3,d3,m3,0]
__global__ void precompute_T23(const float* __restrict__ core2,
                               const float* __restrict__ core3) {
    int comb = blockIdx.x;            // 0..399
    int d2 = comb / 20, d3 = comb % 20;
    for (int e = threadIdx.x; e < 768; e += blockDim.x) {
        int r2 = e / 48;
        int c  = e - r2 * 48;
        int m2 = c >> 3, m3 = c & 7;
        float s = 0.f;
#pragma unroll
        for (int r3 = 0; r3 < 16; ++r3) {
            float v2 = core2[((r2 * 20 + d2) * 6 + m2) * 16 + r3]; // [16,20,6,16]
            float v3 = core3[(r3 * 20 + d3) * 8 + m3];             // [16,20,8,1]
            s += v2 * v3;
        }
        g_T23[comb * 768 + r2 * 48 + c] = s;
    }
}

// ---------------------------------------------------------------------------
// Main kernel: 1 warp per token, 8 tokens per 256-thread block.
// Per token: stage R=[16r][16a] (1KB) and C=[16r][48c] (3KB) into SMEM,
// then each lane computes a 2(a) x 12(c) register tile over K=16.
// ---------------------------------------------------------------------------

#define TOK_PER_BLK 8

__global__ __launch_bounds__(256, 4)
void te_gather_gemm(const int* __restrict__ x, float* __restrict__ out, int B) {
    __shared__ float sR[TOK_PER_BLK][256];   // [r][a]
    __shared__ float sC[TOK_PER_BLK][768];   // [r][c]

    int w    = threadIdx.x >> 5;
    int lane = threadIdx.x & 31;
    int t    = blockIdx.x * TOK_PER_BLK + w;
    if (t >= B) return;

    int idx = x[t];
    int d0  = idx / 4000;  int rem = idx - d0 * 4000;
    int d1  = rem / 400;   rem -= d1 * 400;
    int d2  = rem / 20;    int d3  = rem - d2 * 20;

    // Stage tables into shared memory (float4, fully coalesced)
    const float4* srcR = (const float4*)&g_T01[(d0 * 10 + d1) * 256];
    const float4* srcC = (const float4*)&g_T23[(d2 * 20 + d3) * 768];
    float4* dR = (float4*)sR[w];
    float4* dC = (float4*)sC[w];
    dR[lane]      = srcR[lane];        // 64 float4 total
    dR[lane + 32] = srcR[lane + 32];
#pragma unroll
    for (int i = 0; i < 6; ++i)        // 192 float4 total
        dC[lane + 32 * i] = srcC[lane + 32 * i];
    __syncwarp();

    // Register tile: lane -> a-group of 2 (ag=lane/4), c-group of 12 (cg=lane%4)
    int cg = lane & 3;
    int ag = lane >> 2;
    int a0 = ag * 2;
    int c0 = cg * 12;

    float acc[2][12];
#pragma unroll
    for (int i = 0; i < 2; ++i)
#pragma unroll
        for (int j = 0; j < 12; ++j) acc[i][j] = 0.f;

#pragma unroll
    for (int r = 0; r < 16; ++r) {
        float2 rv  = *(const float2*)&sR[w][r * 16 + a0];
        float4 cv0 = *(const float4*)&sC[w][r * 48 + c0];
        float4 cv1 = *(const float4*)&sC[w][r * 48 + c0 + 4];
        float4 cv2 = *(const float4*)&sC[w][r * 48 + c0 + 8];
        float cv[12] = {cv0.x, cv0.y, cv0.z, cv0.w,
                        cv1.x, cv1.y, cv1.z, cv1.w,
                        cv2.x, cv2.y, cv2.z, cv2.w};
#pragma unroll
        for (int j = 0; j < 12; ++j) {
            acc[0][j] = fmaf(rv.x, cv[j], acc[0][j]);
            acc[1][j] = fmaf(rv.y, cv[j], acc[1][j]);
        }
    }

    // Write: out row is 768 contiguous floats at out + t*768
    float* op = out + (size_t)t * 768;
#pragma unroll
    for (int ai = 0; ai < 2; ++ai) {
        int base = (a0 + ai) * 48 + c0;
        *(float4*)&op[base]     = make_float4(acc[ai][0], acc[ai][1], acc[ai][2],  acc[ai][3]);
        *(float4*)&op[base + 4] = make_float4(acc[ai][4], acc[ai][5], acc[ai][6],  acc[ai][7]);
        *(float4*)&op[base + 8] = make_float4(acc[ai][8], acc[ai][9], acc[ai][10], acc[ai][11]);
    }
}

// ---------------------------------------------------------------------------

extern "C" void kernel_launch(void* const* d_in, const int* in_sizes, int n_in,
                              void* d_out, int out_size) {
    // Identify inputs by element count (robust to ordering):
    // x: B (=32768), core0: 512, core1: 10240, core2: 30720, core3: 2560
    const int*   x  = nullptr;  int B = 0;
    const float* c0 = nullptr;
    const float* c1 = nullptr;
    const float* c2 = nullptr;
    const float* c3 = nullptr;
    for (int i = 0; i < n_in; ++i) {
        switch (in_sizes[i]) {
            case 512:   c0 = (const float*)d_in[i]; break;
            case 10240: c1 = (const float*)d_in[i]; break;
            case 30720: c2 = (const float*)d_in[i]; break;
            case 2560:  c3 = (const float*)d_in[i]; break;
            default:    x  = (const int*)d_in[i]; B = in_sizes[i]; break;
        }
    }

    precompute_T01<<<80, 256>>>(c0, c1);
    precompute_T23<<<400, 256>>>(c2, c3);

    int blocks = (B + TOK_PER_BLK - 1) / TOK_PER_BLK;
    te_gather_gemm<<<blocks, 256>>>(x, (float*)d_out, B);
}

// round 3
// speedup vs baseline: 1.0036x; 1.0036x over previous
#include <cuda_runtime.h>
#include <cuda_bf16.h>

// ---------------------------------------------------------------------------
// TensorizedEmbedding: out[b] = core0[d0] x core1[d1] x core2[d2] x core3[d3]
// ROW_DIMS=(8,10,20,20), COL_DIMS=(4,4,6,8), RANKS=(1,16,16,16,1)
// Strategy: pre-contract into T01[80][16r][16a] and T23[400][16r][48c],
// then per token a 16x48x16 GEMM from shared memory using packed f32x2 FMA.
// ---------------------------------------------------------------------------

static __device__ float g_T01[80 * 256];    // [(d0*10+d1)][r2][a]  (a = m0*4+m1)
static __device__ float g_T23[400 * 768];   // [(d2*20+d3)][r2][c]  (c = m2*8+m3)

// Fused precompute: blocks 0..79 build T01, blocks 80..479 build T23.
__global__ void precompute_tables(const float* __restrict__ core0,
                                  const float* __restrict__ core1,
                                  const float* __restrict__ core2,
                                  const float* __restrict__ core3) {
    if (blockIdx.x < 80) {
        // T01[comb][r2][a] = sum_{r1} core0[0,d0,m0,r1] * core1[r1,d1,m1,r2]
        int comb = blockIdx.x;
        int d0 = comb / 10, d1 = comb % 10;
        int e  = threadIdx.x;             // 0..255
        int r2 = e >> 4;
        int a  = e & 15;                  // m0*4 + m1
        int m0 = a >> 2, m1 = a & 3;
        float s = 0.f;
#pragma unroll
        for (int r1 = 0; r1 < 16; ++r1) {
            float v0 = core0[(d0 * 4 + m0) * 16 + r1];             // [1,8,4,16]
            float v1 = core1[((r1 * 10 + d1) * 4 + m1) * 16 + r2]; // [16,10,4,16]
            s += v0 * v1;
        }
        g_T01[comb * 256 + r2 * 16 + a] = s;
    } else {
        // T23[comb][r2][c] = sum_{r3} core2[r2,d2,m2,r3] * core3[r3,d3,m3,0]
        int comb = blockIdx.x - 80;       // 0..399
        int d2 = comb / 20, d3 = comb % 20;
        for (int e = threadIdx.x; e < 768; e += blockDim.x) {
            int r2 = e / 48;
            int c  = e - r2 * 48;
            int m2 = c >> 3, m3 = c & 7;
            float s = 0.f;
#pragma unroll
            for (int r3 = 0; r3 < 16; ++r3) {
                float v2 = core2[((r2 * 20 + d2) * 6 + m2) * 16 + r3]; // [16,20,6,16]
                float v3 = core3[(r3 * 20 + d3) * 8 + m3];             // [16,20,8,1]
                s += v2 * v3;
            }
            g_T23[comb * 768 + r2 * 48 + c] = s;
        }
    }
}

// ---------------------------------------------------------------------------
// Main kernel: 1 warp per token, 8 tokens per 256-thread block.
// Per token: stage R=[16r][16a] (1KB) and C=[16r][48c] (3KB) into SMEM,
// then each lane computes a 2(a) x 12(c) register tile over K=16 using
// fma.rn.f32x2 (packed along c: 6 u64 accumulators per a-row).
// ---------------------------------------------------------------------------

#define TOK_PER_BLK 8

__device__ __forceinline__ unsigned long long pack_dup(float v) {
    unsigned long long r;
    asm("mov.b64 %0, {%1, %1};" : "=l"(r) : "f"(v));
    return r;
}

__device__ __forceinline__ void fma2(unsigned long long& d,
                                     unsigned long long a,
                                     unsigned long long b) {
    asm("fma.rn.f32x2 %0, %1, %2, %0;" : "+l"(d) : "l"(a), "l"(b));
}

__device__ __forceinline__ void stcs128(float* p, unsigned long long lo,
                                        unsigned long long hi) {
    asm volatile("st.global.cs.v2.b64 [%0], {%1, %2};"
                 :: "l"(p), "l"(lo), "l"(hi) : "memory");
}

__global__ __launch_bounds__(256, 4)
void te_gather_gemm(const int* __restrict__ x, float* __restrict__ out, int B) {
    __shared__ float sR[TOK_PER_BLK][256];   // [r][a]
    __shared__ float sC[TOK_PER_BLK][768];   // [r][c]

    int w    = threadIdx.x >> 5;
    int lane = threadIdx.x & 31;
    int t    = blockIdx.x * TOK_PER_BLK + w;
    if (t >= B) return;

    int idx = x[t];
    int d0  = idx / 4000;  int rem = idx - d0 * 4000;
    int d1  = rem / 400;   rem -= d1 * 400;
    int d2  = rem / 20;    int d3  = rem - d2 * 20;

    // Stage tables into shared memory (float4, fully coalesced)
    const float4* srcR = (const float4*)&g_T01[(d0 * 10 + d1) * 256];
    const float4* srcC = (const float4*)&g_T23[(d2 * 20 + d3) * 768];
    float4* dR = (float4*)sR[w];
    float4* dC = (float4*)sC[w];
    dR[lane]      = srcR[lane];        // 64 float4 total
    dR[lane + 32] = srcR[lane + 32];
#pragma unroll
    for (int i = 0; i < 6; ++i)        // 192 float4 total
        dC[lane + 32 * i] = srcC[lane + 32 * i];
    __syncwarp();

    // Register tile: lane -> a-group of 2 (ag=lane/4), c-group of 12 (cg=lane%4)
    int cg = lane & 3;
    int ag = lane >> 2;
    int a0 = ag * 2;
    int c0 = cg * 12;

    // Packed accumulators: accA = row a0, accB = row a0+1; 6 f32x2 pairs each.
    unsigned long long accA[6], accB[6];
#pragma unroll
    for (int j = 0; j < 6; ++j) { accA[j] = 0ull; accB[j] = 0ull; }

#pragma unroll
    for (int r = 0; r < 16; ++r) {
        float2 rv = *(const float2*)&sR[w][r * 16 + a0];
        unsigned long long rx = pack_dup(rv.x);
        unsigned long long ry = pack_dup(rv.y);
        // 12 c-values = 3 LDS.128 = 6 packed u64 pairs
        ulonglong2 p0 = *(const ulonglong2*)&sC[w][r * 48 + c0];
        ulonglong2 p1 = *(const ulonglong2*)&sC[w][r * 48 + c0 + 4];
        ulonglong2 p2 = *(const ulonglong2*)&sC[w][r * 48 + c0 + 8];
        fma2(accA[0], rx, p0.x);  fma2(accB[0], ry, p0.x);
        fma2(accA[1], rx, p0.y);  fma2(accB[1], ry, p0.y);
        fma2(accA[2], rx, p1.x);  fma2(accB[2], ry, p1.x);
        fma2(accA[3], rx, p1.y);  fma2(accB[3], ry, p1.y);
        fma2(accA[4], rx, p2.x);  fma2(accB[4], ry, p2.x);
        fma2(accA[5], rx, p2.y);  fma2(accB[5], ry, p2.y);
    }

    // Write: out row is 768 contiguous floats at out + t*768 (streaming stores)
    float* op = out + (size_t)t * 768;
    int baseA = a0 * 48 + c0;
    int baseB = baseA + 48;
    stcs128(&op[baseA],     accA[0], accA[1]);
    stcs128(&op[baseA + 4], accA[2], accA[3]);
    stcs128(&op[baseA + 8], accA[4], accA[5]);
    stcs128(&op[baseB],     accB[0], accB[1]);
    stcs128(&op[baseB + 4], accB[2], accB[3]);
    stcs128(&op[baseB + 8], accB[4], accB[5]);
}

// ---------------------------------------------------------------------------

extern "C" void kernel_launch(void* const* d_in, const int* in_sizes, int n_in,
                              void* d_out, int out_size) {
    // Identify inputs by element count (robust to ordering):
    // x: B (=32768), core0: 512, core1: 10240, core2: 30720, core3: 2560
    const int*   x  = nullptr;  int B = 0;
    const float* c0 = nullptr;
    const float* c1 = nullptr;
    const float* c2 = nullptr;
    const float* c3 = nullptr;
    for (int i = 0; i < n_in; ++i) {
        switch (in_sizes[i]) {
            case 512:   c0 = (const float*)d_in[i]; break;
            case 10240: c1 = (const float*)d_in[i]; break;
            case 30720: c2 = (const float*)d_in[i]; break;
            case 2560:  c3 = (const float*)d_in[i]; break;
            default:    x  = (const int*)d_in[i]; B = in_sizes[i]; break;
        }
    }

    precompute_tables<<<480, 256>>>(c0, c1, c2, c3);

    int blocks = (B + TOK_PER_BLK - 1) / TOK_PER_BLK;
    te_gather_gemm<<<blocks, 256>>>(x, (float*)d_out, B);
}